// round 3
// baseline (speedup 1.0000x reference)
#include <cuda_runtime.h>
#include <cstdint>

#define S_LEN 2048
#define BATCH 32
#define HID   256
#define NCOL  1024   // 4*H

// 256 MB scratch for Zx = x @ Wx + b, layout [s][b][j]
__device__ float g_zx[(size_t)S_LEN * BATCH * NCOL];

// ----------------------------- helpers -----------------------------
__device__ __forceinline__ void fma2(unsigned long long &d, unsigned long long a, unsigned long long b) {
    asm("fma.rn.f32x2 %0, %1, %2, %0;" : "+l"(d) : "l"(a), "l"(b));
}
__device__ __forceinline__ unsigned long long pack2(float lo, float hi) {
    unsigned long long r; asm("mov.b64 %0, {%1, %2};" : "=l"(r) : "f"(lo), "f"(hi)); return r;
}
__device__ __forceinline__ float lo32(unsigned long long v){ return __uint_as_float((unsigned)(v & 0xffffffffull)); }
__device__ __forceinline__ float hi32(unsigned long long v){ return __uint_as_float((unsigned)(v >> 32)); }
__device__ __forceinline__ unsigned smem_u32(const void* p){ return (unsigned)__cvta_generic_to_shared(p); }
__device__ __forceinline__ void cp_async4(unsigned dst, const void* src){
    asm volatile("cp.async.ca.shared.global [%0], [%1], 4;" :: "r"(dst), "l"(src));
}
__device__ __forceinline__ void cp_commit(){ asm volatile("cp.async.commit_group;" ::: "memory"); }
__device__ __forceinline__ void cp_wait1(){ asm volatile("cp.async.wait_group 1;" ::: "memory"); }
__device__ __forceinline__ unsigned mapa_rank(unsigned a, unsigned rk){
    unsigned r; asm("mapa.shared::cluster.u32 %0, %1, %2;" : "=r"(r) : "r"(a), "r"(rk)); return r;
}
__device__ __forceinline__ void st_cluster(unsigned a, float v){
    asm volatile("st.shared::cluster.f32 [%0], %1;" :: "r"(a), "f"(v) : "memory");
}
__device__ __forceinline__ void cluster_sync_(){
    asm volatile("barrier.cluster.arrive.aligned;" ::: "memory");
    asm volatile("barrier.cluster.wait.aligned;" ::: "memory");
}
__device__ __forceinline__ float sigmoidf_(float x){ return __fdividef(1.0f, 1.0f + __expf(-x)); }

// ----------------------------- phase 0: zero the two trailing zero-tensors -----------------------------
__global__ void zero_tail_kernel(float* __restrict__ out, long long start, long long n) {
    long long i = (long long)blockIdx.x * blockDim.x + threadIdx.x;
    if (i < n) out[start + i] = 0.0f;
}

// ----------------------------- phase 1: Zx = x @ Wx + b -----------------------------
// M = 65536 (row r = s*32 + b), N = 1024, K = 256. 128x128 tile, 8x8 microtile.
__global__ void __launch_bounds__(256, 2)
gemm_x_kernel(const float* __restrict__ x, const float* __restrict__ W, const float* __restrict__ bias)
{
    __shared__ float As[32][128];   // [k][row]
    __shared__ float Bs[32][128];   // [k][col]

    const int tid = threadIdx.x;
    const int colTile = blockIdx.x * 128;
    const int rowTile = blockIdx.y * 128;
    const int tx = tid & 15, ty = tid >> 4;

    float acc[8][8];
    #pragma unroll
    for (int i = 0; i < 8; i++)
        #pragma unroll
        for (int j = 0; j < 8; j++) acc[i][j] = 0.0f;

    const int arow = tid >> 3;          // 0..31
    const int akk  = (tid & 7) * 4;     // 0..28
    const int bkk  = tid >> 3;          // 0..31
    const int bj   = (tid & 7) * 16;    // 0..112

    for (int k0 = 0; k0 < 256; k0 += 32) {
        #pragma unroll
        for (int wv = 0; wv < 4; wv++) {
            int row = arow + wv * 32;
            int rr  = rowTile + row;
            int bb  = rr & 31;          // batch
            int ss  = rr >> 5;          // seq pos
            float4 v = *(const float4*)&x[((size_t)bb * S_LEN + ss) * 256 + k0 + akk];
            As[akk + 0][row] = v.x; As[akk + 1][row] = v.y;
            As[akk + 2][row] = v.z; As[akk + 3][row] = v.w;
        }
        #pragma unroll
        for (int wv = 0; wv < 4; wv++) {
            float4 v = *(const float4*)&W[(size_t)(k0 + bkk) * NCOL + colTile + bj + wv * 4];
            *(float4*)&Bs[bkk][bj + wv * 4] = v;
        }
        __syncthreads();

        #pragma unroll
        for (int kk = 0; kk < 32; kk++) {
            float a[8], b8[8];
            *(float4*)&a[0]  = *(const float4*)&As[kk][ty * 8];
            *(float4*)&a[4]  = *(const float4*)&As[kk][ty * 8 + 4];
            *(float4*)&b8[0] = *(const float4*)&Bs[kk][tx * 8];
            *(float4*)&b8[4] = *(const float4*)&Bs[kk][tx * 8 + 4];
            #pragma unroll
            for (int i = 0; i < 8; i++)
                #pragma unroll
                for (int j = 0; j < 8; j++)
                    acc[i][j] = fmaf(a[i], b8[j], acc[i][j]);
        }
        __syncthreads();
    }

    float bv[8];
    #pragma unroll
    for (int j = 0; j < 8; j++) bv[j] = bias[colTile + tx * 8 + j];

    #pragma unroll
    for (int i = 0; i < 8; i++) {
        size_t rr = (size_t)rowTile + ty * 8 + i;
        float4 o0, o1;
        o0.x = acc[i][0] + bv[0]; o0.y = acc[i][1] + bv[1];
        o0.z = acc[i][2] + bv[2]; o0.w = acc[i][3] + bv[3];
        o1.x = acc[i][4] + bv[4]; o1.y = acc[i][5] + bv[5];
        o1.z = acc[i][6] + bv[6]; o1.w = acc[i][7] + bv[7];
        *(float4*)&g_zx[rr * NCOL + colTile + tx * 8]     = o0;
        *(float4*)&g_zx[rr * NCOL + colTile + tx * 8 + 4] = o1;
    }
}

// ----------------------------- phase 2: the recurrence -----------------------------
// 16 clusters x 8 CTAs. Cluster c owns chains b0=2c, b1=2c+1. CTA rank r owns
// h-indices [r*32, r*32+32) and the 128 z-columns {g*256 + r*32 + m}.
// Wh slice (128 cols x 256 k) lives in registers as f32x2 pairs over k,
// shared by both chains. h is cluster-replicated in SMEM (double-buffered by
// step parity); each CTA broadcasts its 64 new h values via st.shared::cluster.
__global__ void __cluster_dims__(8, 1, 1) __launch_bounds__(512, 1)
lstm_chain_kernel(const float* __restrict__ W, const float* __restrict__ h0,
                  const float* __restrict__ c0, float* __restrict__ out)
{
    __shared__ __align__(16) float h_buf[2][2][HID];  // [parity][chain][k]
    __shared__ float red[4][256];                     // [kq][chain*128 + col]
    __shared__ float zsm[2][128];                     // [chain][col]
    __shared__ float zx_s[2][2][128];                 // [parity][chain][col]

    const int tid = threadIdx.x;
    const int p = blockIdx.x >> 3;     // chain-pair id 0..15
    const int r = blockIdx.x & 7;      // cluster rank 0..7

    // FMA-phase mapping: warp -> (kq, gate), lane -> m
    const int warp  = tid >> 5;
    const int kq    = warp >> 2;                 // k quarter 0..3
    const int colg  = warp & 3;                  // gate 0..3
    const int lane  = tid & 31;                  // m
    const int colF  = colg * 32 + lane;          // 0..127
    const int jF    = colg * 256 + r * 32 + lane;
    const int kbase = kq * 64;

    // preload weights: 32 packed pairs over k (64 regs)
    unsigned long long w[32];
    {
        const float* Wh = W + (size_t)(256 + kbase) * NCOL + jF;
        #pragma unroll
        for (int q = 0; q < 32; q++) {
            float a  = Wh[(size_t)(2 * q)     * NCOL];
            float b2 = Wh[(size_t)(2 * q + 1) * NCOL];
            w[q] = pack2(a, b2);
        }
    }

    // init h_buf[0]
    {
        int c = tid >> 8, k = tid & 255;
        h_buf[0][c][k] = h0[(size_t)(2 * p + c) * HID + k];
    }
    // cell state owners (tid < 64): (chain, m)
    const int oc = tid >> 5;
    const int om = tid & 31;
    float cst = 0.0f;
    if (tid < 64) cst = c0[(size_t)(2 * p + oc) * HID + r * 32 + om];

    // prefetch mapping (tid < 256): (chain, col)
    const int pc   = tid >> 7;
    const int pcol = tid & 127;
    const int pj   = (pcol >> 5) * 256 + r * 32 + (pcol & 31);
    const float* zx_src = g_zx + (size_t)(2 * p + pc) * NCOL + pj;

    __syncthreads();
    cluster_sync_();   // all CTAs alive + h_buf[0] init ordered before DSMEM use

    if (tid < 256) {
        cp_async4(smem_u32(&zx_s[0][pc][pcol]), zx_src);  // step 0
        cp_commit();
    }

    for (int s = 0; s < S_LEN; s++) {
        const int par = s & 1;

        if (tid < 256) {
            if (s + 1 < S_LEN)
                cp_async4(smem_u32(&zx_s[par ^ 1][pc][pcol]),
                          zx_src + (size_t)(s + 1) * (BATCH * NCOL));
            cp_commit();
        }

        // Wh . h for both chains, f32x2 SIMD over k
        unsigned long long acc0 = 0ull, acc1 = 0ull;
        const float* hb0 = &h_buf[par][0][kbase];
        const float* hb1 = &h_buf[par][1][kbase];
        #pragma unroll
        for (int i = 0; i < 16; i++) {
            ulonglong2 hp0 = *(const ulonglong2*)(hb0 + 4 * i);
            ulonglong2 hp1 = *(const ulonglong2*)(hb1 + 4 * i);
            fma2(acc0, w[2 * i],     hp0.x);
            fma2(acc0, w[2 * i + 1], hp0.y);
            fma2(acc1, w[2 * i],     hp1.x);
            fma2(acc1, w[2 * i + 1], hp1.y);
        }
        red[kq][colF]       = lo32(acc0) + hi32(acc0);
        red[kq][128 + colF] = lo32(acc1) + hi32(acc1);
        __syncthreads();

        if (tid < 256) {
            float sum = red[0][tid] + red[1][tid] + red[2][tid] + red[3][tid];
            cp_wait1();   // step-s zx ready (issued by this same thread)
            float z = tanhf(sum + zx_s[par][pc][pcol]);
            zsm[pc][pcol] = z;
        }
        __syncthreads();

        if (tid < 64) {
            float iv = sigmoidf_(zsm[oc][om]);
            float fv = sigmoidf_(zsm[oc][32 + om]);
            float gv = tanhf(zsm[oc][64 + om]);
            float ov = sigmoidf_(zsm[oc][96 + om]);
            cst = fv * cst + iv * gv;
            float hn = tanhf(cst) * ov;
            out[((size_t)(2 * p + oc) * S_LEN + s) * HID + r * 32 + om] = hn;
            // broadcast new h to every CTA in the cluster (incl. self)
            unsigned la = smem_u32(&h_buf[par ^ 1][oc][r * 32 + om]);
            #pragma unroll
            for (int rk = 0; rk < 8; rk++) st_cluster(mapa_rank(la, rk), hn);
        }
        cluster_sync_();  // release stores / acquire for next step
    }
}

// ----------------------------- launcher -----------------------------
extern "C" void kernel_launch(void* const* d_in, const int* in_sizes, int n_in,
                              void* d_out, int out_size) {
    const float* x    = (const float*)d_in[0];   // (32, 2048, 256)
    const float* h0   = (const float*)d_in[1];   // (1, 32, 256)
    const float* c0   = (const float*)d_in[2];   // (1, 32, 256)
    const float* W    = (const float*)d_in[3];   // (512, 1024)
    const float* bias = (const float*)d_in[4];   // (1024,)
    float* out = (float*)d_out;

    const long long main_elems = (long long)BATCH * S_LEN * HID;  // 16,777,216
    const long long tail = (long long)out_size - main_elems;      // the two zero tensors
    if (tail > 0) {
        int blocks = (int)((tail + 255) / 256);
        zero_tail_kernel<<<blocks, 256>>>(out, main_elems, tail);
    }

    gemm_x_kernel<<<dim3(8, 512, 1), 256>>>(x, W, bias);
    lstm_chain_kernel<<<128, 512>>>(W, h0, c0, out);
}